// round 16
// baseline (speedup 1.0000x reference)
#include <cuda_runtime.h>
#include <cuda_bf16.h>
#include <cstdint>
#include <math_constants.h>

// out = softmax(Q K^T) V, N=4096, D=1024, fp32.
//   K0: VT = V^T
//   K1: S  = Q K^T   (mma.sync tf32x3; hi/lo split precomputed into smem)
//   K2: row softmax on S
//   K3: out = P VT^T (mma.sync bf16x3; safe because P rows sum to 1)
// Split-at-copy removes the cvt/sub ALU storm from the mainloop (ncu: alu=27.5%).

#define NTOK 4096
#define DDIM 1024
#define BK 32

__device__ float g_S[(size_t)NTOK * (size_t)NTOK];   // 64 MB scores
__device__ float g_VT[(size_t)DDIM * (size_t)NTOK];  // 16 MB V^T

// ---------------------------------------------------------------------------
__device__ __forceinline__ uint32_t f2tf(float x) {
    uint32_t u;
    asm("cvt.rna.tf32.f32 %0, %1;" : "=r"(u) : "f"(x));
    return u;
}
__device__ __forceinline__ uint32_t bf16b(float x) {
    __nv_bfloat16 b = __float2bfloat16(x);
    return (uint32_t)*(uint16_t*)&b;
}

__device__ __forceinline__ void mma_tf32(float* c, const uint32_t* a,
                                         const uint32_t* b) {
    asm volatile(
        "mma.sync.aligned.m16n8k8.row.col.f32.tf32.tf32.f32 "
        "{%0,%1,%2,%3}, {%4,%5,%6,%7}, {%8,%9}, {%0,%1,%2,%3};"
        : "+f"(c[0]), "+f"(c[1]), "+f"(c[2]), "+f"(c[3])
        : "r"(a[0]), "r"(a[1]), "r"(a[2]), "r"(a[3]), "r"(b[0]), "r"(b[1]));
}
__device__ __forceinline__ void mma_bf16(float* c, const uint32_t* a,
                                         const uint32_t* b) {
    asm volatile(
        "mma.sync.aligned.m16n8k16.row.col.f32.bf16.bf16.f32 "
        "{%0,%1,%2,%3}, {%4,%5,%6,%7}, {%8,%9}, {%0,%1,%2,%3};"
        : "+f"(c[0]), "+f"(c[1]), "+f"(c[2]), "+f"(c[3])
        : "r"(a[0]), "r"(a[1]), "r"(a[2]), "r"(a[3]), "r"(b[0]), "r"(b[1]));
}

// ===========================================================================
// S = Q K^T  (tf32x3).  smem: interleaved (hi,lo) fp32 planes.
// Row stride TS=72 floats (64 data + 8 pad): 72 mod 32 = 8 -> fragment LDS.64
// banks (8g+2kq) are conflict-free.
// ===========================================================================
#define TS 72
#define T_TILE (128 * TS)
#define T_STAGE (2 * T_TILE)
#define T_SMEM (2 * T_STAGE * 4)   // 147456 B

__global__ __launch_bounds__(256, 1)
void gemm_s_tf32(const float* __restrict__ A, int lda,
                 const float* __restrict__ B, int ldb,
                 float* __restrict__ C, int ldc, int kIters)
{
    extern __shared__ float smf[];
    const int tid  = threadIdx.x;
    const int wid  = tid >> 5;
    const int lane = tid & 31;
    const int g    = lane >> 2;
    const int kq   = lane & 3;
    const int wm   = wid & 1;
    const int wn   = wid >> 1;
    const int m0   = blockIdx.y * 128;
    const int n0   = blockIdx.x * 128;

    int crow[4], ccol[4];
#pragma unroll
    for (int t = 0; t < 4; t++) {
        int idx = tid + 256 * t;
        crow[t] = idx >> 3;
        ccol[t] = idx & 7;
    }

    float4 ra[4], rb[4];
    auto load_regs = [&](int j) {
        const int k0 = j * BK;
#pragma unroll
        for (int t = 0; t < 4; t++) {
            ra[t] = *(const float4*)(A + (size_t)(m0 + crow[t]) * lda + k0 + ccol[t] * 4);
            rb[t] = *(const float4*)(B + (size_t)(n0 + crow[t]) * ldb + k0 + ccol[t] * 4);
        }
    };
    auto split4 = [](float4 f, float* o) {
        uint32_t h;
        h = f2tf(f.x); o[0] = __uint_as_float(h); o[1] = __uint_as_float(f2tf(f.x - __uint_as_float(h)));
        h = f2tf(f.y); o[2] = __uint_as_float(h); o[3] = __uint_as_float(f2tf(f.y - __uint_as_float(h)));
        h = f2tf(f.z); o[4] = __uint_as_float(h); o[5] = __uint_as_float(f2tf(f.z - __uint_as_float(h)));
        h = f2tf(f.w); o[6] = __uint_as_float(h); o[7] = __uint_as_float(f2tf(f.w - __uint_as_float(h)));
    };
    auto sts_stage = [&](int buf) {
        float* base = smf + buf * T_STAGE;
#pragma unroll
        for (int t = 0; t < 4; t++) {
            float o[8];
            float* pa = base + crow[t] * TS + ccol[t] * 8;
            split4(ra[t], o);
            *(float4*)(pa)     = make_float4(o[0], o[1], o[2], o[3]);
            *(float4*)(pa + 4) = make_float4(o[4], o[5], o[6], o[7]);
            float* pb = pa + T_TILE;
            split4(rb[t], o);
            *(float4*)(pb)     = make_float4(o[0], o[1], o[2], o[3]);
            *(float4*)(pb + 4) = make_float4(o[4], o[5], o[6], o[7]);
        }
    };

    float acc[4][4][4];
#pragma unroll
    for (int mt = 0; mt < 4; mt++)
#pragma unroll
        for (int nt = 0; nt < 4; nt++)
#pragma unroll
            for (int r = 0; r < 4; r++) acc[mt][nt][r] = 0.f;

    load_regs(0);
    sts_stage(0);
    __syncthreads();

    for (int i = 0; i < kIters; i++) {
        if (i + 1 < kIters) load_regs(i + 1);

        const float* As = smf + (i & 1) * T_STAGE;
        const float* Bs = As + T_TILE;
#pragma unroll
        for (int k8 = 0; k8 < BK / 8; k8++) {
            const int kc = k8 * 8 + kq;
            uint32_t Ahi[4][4], Alo[4][4], Bhi[4][2], Blo[4][2];
#pragma unroll
            for (int mt = 0; mt < 4; mt++) {
                const int r0 = wm * 64 + mt * 16 + g;
                uint2 u0 = *(const uint2*)&As[r0 * TS + 2 * kc];
                uint2 u1 = *(const uint2*)&As[(r0 + 8) * TS + 2 * kc];
                uint2 u2 = *(const uint2*)&As[r0 * TS + 2 * (kc + 4)];
                uint2 u3 = *(const uint2*)&As[(r0 + 8) * TS + 2 * (kc + 4)];
                Ahi[mt][0] = u0.x; Alo[mt][0] = u0.y;
                Ahi[mt][1] = u1.x; Alo[mt][1] = u1.y;
                Ahi[mt][2] = u2.x; Alo[mt][2] = u2.y;
                Ahi[mt][3] = u3.x; Alo[mt][3] = u3.y;
            }
#pragma unroll
            for (int nt = 0; nt < 4; nt++) {
                const int n = wn * 32 + nt * 8 + g;
                uint2 v0 = *(const uint2*)&Bs[n * TS + 2 * kc];
                uint2 v1 = *(const uint2*)&Bs[n * TS + 2 * (kc + 4)];
                Bhi[nt][0] = v0.x; Blo[nt][0] = v0.y;
                Bhi[nt][1] = v1.x; Blo[nt][1] = v1.y;
            }
#pragma unroll
            for (int mt = 0; mt < 4; mt++)
#pragma unroll
                for (int nt = 0; nt < 4; nt++) {
                    mma_tf32(acc[mt][nt], Ahi[mt], Bhi[nt]);
                    mma_tf32(acc[mt][nt], Ahi[mt], Blo[nt]);
                    mma_tf32(acc[mt][nt], Alo[mt], Bhi[nt]);
                }
        }

        if (i + 1 < kIters) sts_stage((i + 1) & 1);
        __syncthreads();
    }

#pragma unroll
    for (int mt = 0; mt < 4; mt++) {
        const int r0 = m0 + wm * 64 + mt * 16 + g;
#pragma unroll
        for (int nt = 0; nt < 4; nt++) {
            const int col = n0 + wn * 32 + nt * 8 + kq * 2;
            *(float2*)(C + (size_t)r0 * ldc + col)       = make_float2(acc[mt][nt][0], acc[mt][nt][1]);
            *(float2*)(C + (size_t)(r0 + 8) * ldc + col) = make_float2(acc[mt][nt][2], acc[mt][nt][3]);
        }
    }
}

// ===========================================================================
// out = P VT^T  (bf16x3).  smem: per k-pair, (hi_pack, lo_pack) u32 pairs.
// Row stride BS=40 u32 (32 data + 8 pad): banks (8g+2kq) conflict-free.
// ===========================================================================
#define BS 40
#define B_TILE (128 * BS)
#define B_STAGE (2 * B_TILE)
#define B_SMEM (2 * B_STAGE * 4)   // 81920 B

__global__ __launch_bounds__(256, 1)
void gemm_pv_bf16(const float* __restrict__ A, int lda,
                  const float* __restrict__ B, int ldb,
                  float* __restrict__ C, int ldc, int kIters)
{
    extern __shared__ uint32_t smu[];
    const int tid  = threadIdx.x;
    const int wid  = tid >> 5;
    const int lane = tid & 31;
    const int g    = lane >> 2;
    const int kq   = lane & 3;
    const int wm   = wid & 1;
    const int wn   = wid >> 1;
    const int m0   = blockIdx.y * 128;
    const int n0   = blockIdx.x * 128;

    int crow[4], ccol[4];
#pragma unroll
    for (int t = 0; t < 4; t++) {
        int idx = tid + 256 * t;
        crow[t] = idx >> 3;
        ccol[t] = idx & 7;
    }

    float4 ra[4], rb[4];
    auto load_regs = [&](int j) {
        const int k0 = j * BK;
#pragma unroll
        for (int t = 0; t < 4; t++) {
            ra[t] = *(const float4*)(A + (size_t)(m0 + crow[t]) * lda + k0 + ccol[t] * 4);
            rb[t] = *(const float4*)(B + (size_t)(n0 + crow[t]) * ldb + k0 + ccol[t] * 4);
        }
    };
    // float4 (k..k+3) -> {hi(k,k+1), lo(k,k+1), hi(k+2,k+3), lo(k+2,k+3)}
    auto split4 = [](float4 f, uint32_t* o) {
        uint32_t hx = bf16b(f.x), hy = bf16b(f.y);
        uint32_t lx = bf16b(f.x - __bfloat162float(*(__nv_bfloat16*)&hx));
        uint32_t ly = bf16b(f.y - __bfloat162float(*(__nv_bfloat16*)&hy));
        o[0] = hx | (hy << 16);
        o[1] = lx | (ly << 16);
        uint32_t hz = bf16b(f.z), hw = bf16b(f.w);
        uint32_t lz = bf16b(f.z - __bfloat162float(*(__nv_bfloat16*)&hz));
        uint32_t lw = bf16b(f.w - __bfloat162float(*(__nv_bfloat16*)&hw));
        o[2] = hz | (hw << 16);
        o[3] = lz | (lw << 16);
    };
    auto sts_stage = [&](int buf) {
        uint32_t* base = smu + buf * B_STAGE;
#pragma unroll
        for (int t = 0; t < 4; t++) {
            uint32_t o[4];
            split4(ra[t], o);
            *(uint4*)(base + crow[t] * BS + ccol[t] * 4) = make_uint4(o[0], o[1], o[2], o[3]);
            split4(rb[t], o);
            *(uint4*)(base + B_TILE + crow[t] * BS + ccol[t] * 4) = make_uint4(o[0], o[1], o[2], o[3]);
        }
    };

    float acc[4][4][4];
#pragma unroll
    for (int mt = 0; mt < 4; mt++)
#pragma unroll
        for (int nt = 0; nt < 4; nt++)
#pragma unroll
            for (int r = 0; r < 4; r++) acc[mt][nt][r] = 0.f;

    load_regs(0);
    sts_stage(0);
    __syncthreads();

    for (int i = 0; i < kIters; i++) {
        if (i + 1 < kIters) load_regs(i + 1);

        const uint32_t* As = smu + (i & 1) * B_STAGE;
        const uint32_t* Bs = As + B_TILE;
#pragma unroll
        for (int j = 0; j < BK / 16; j++) {          // 2 k16 steps
            const int p  = j * 8 + kq;               // pair index
            uint32_t Ahi[4][4], Alo[4][4], Bhi[4][2], Blo[4][2];
#pragma unroll
            for (int mt = 0; mt < 4; mt++) {
                const int r0 = wm * 64 + mt * 16 + g;
                uint2 u0 = *(const uint2*)&As[r0 * BS + 2 * p];
                uint2 u1 = *(const uint2*)&As[(r0 + 8) * BS + 2 * p];
                uint2 u2 = *(const uint2*)&As[r0 * BS + 2 * (p + 4)];
                uint2 u3 = *(const uint2*)&As[(r0 + 8) * BS + 2 * (p + 4)];
                Ahi[mt][0] = u0.x; Alo[mt][0] = u0.y;
                Ahi[mt][1] = u1.x; Alo[mt][1] = u1.y;
                Ahi[mt][2] = u2.x; Alo[mt][2] = u2.y;
                Ahi[mt][3] = u3.x; Alo[mt][3] = u3.y;
            }
#pragma unroll
            for (int nt = 0; nt < 4; nt++) {
                const int n = wn * 32 + nt * 8 + g;
                uint2 v0 = *(const uint2*)&Bs[n * BS + 2 * p];
                uint2 v1 = *(const uint2*)&Bs[n * BS + 2 * (p + 4)];
                Bhi[nt][0] = v0.x; Blo[nt][0] = v0.y;
                Bhi[nt][1] = v1.x; Blo[nt][1] = v1.y;
            }
#pragma unroll
            for (int mt = 0; mt < 4; mt++)
#pragma unroll
                for (int nt = 0; nt < 4; nt++) {
                    mma_bf16(acc[mt][nt], Ahi[mt], Bhi[nt]);
                    mma_bf16(acc[mt][nt], Ahi[mt], Blo[nt]);
                    mma_bf16(acc[mt][nt], Alo[mt], Bhi[nt]);
                }
        }

        if (i + 1 < kIters) sts_stage((i + 1) & 1);
        __syncthreads();
    }

#pragma unroll
    for (int mt = 0; mt < 4; mt++) {
        const int r0 = m0 + wm * 64 + mt * 16 + g;
#pragma unroll
        for (int nt = 0; nt < 4; nt++) {
            const int col = n0 + wn * 32 + nt * 8 + kq * 2;
            *(float2*)(C + (size_t)r0 * ldc + col)       = make_float2(acc[mt][nt][0], acc[mt][nt][1]);
            *(float2*)(C + (size_t)(r0 + 8) * ldc + col) = make_float2(acc[mt][nt][2], acc[mt][nt][3]);
        }
    }
}

// ---------------------------------------------------------------------------
__global__ __launch_bounds__(256)
void transpose_kernel(const float* __restrict__ in, float* __restrict__ out,
                      int R, int Ccols)
{
    __shared__ float t[32][33];
    const int r0 = blockIdx.y * 32, c0 = blockIdx.x * 32;
    const int x = threadIdx.x & 31, y = threadIdx.x >> 5;
#pragma unroll
    for (int i = 0; i < 32; i += 8)
        t[y + i][x] = in[(size_t)(r0 + y + i) * Ccols + c0 + x];
    __syncthreads();
#pragma unroll
    for (int i = 0; i < 32; i += 8)
        out[(size_t)(c0 + y + i) * R + r0 + x] = t[x][y + i];
}

// ---------------------------------------------------------------------------
__global__ __launch_bounds__(256)
void softmax_kernel(float* __restrict__ S, int N)
{
    __shared__ float red[8];
    const int t    = threadIdx.x;
    const int lane = t & 31;
    const int wid  = t >> 5;
    float4* p4 = (float4*)(S + (size_t)blockIdx.x * N);
    const int n4 = N / 4;

    float m = -CUDART_INF_F;
    for (int i = t; i < n4; i += 256) {
        float4 vv = p4[i];
        m = fmaxf(m, fmaxf(fmaxf(vv.x, vv.y), fmaxf(vv.z, vv.w)));
    }
#pragma unroll
    for (int s = 16; s > 0; s >>= 1)
        m = fmaxf(m, __shfl_xor_sync(0xffffffffu, m, s));
    if (lane == 0) red[wid] = m;
    __syncthreads();
    m = red[0];
#pragma unroll
    for (int w = 1; w < 8; w++) m = fmaxf(m, red[w]);

    float sum = 0.f;
    for (int i = t; i < n4; i += 256) {
        float4 vv = p4[i];
        vv.x = __expf(vv.x - m);
        vv.y = __expf(vv.y - m);
        vv.z = __expf(vv.z - m);
        vv.w = __expf(vv.w - m);
        sum += (vv.x + vv.y) + (vv.z + vv.w);
        p4[i] = vv;
    }
#pragma unroll
    for (int s = 16; s > 0; s >>= 1)
        sum += __shfl_xor_sync(0xffffffffu, sum, s);
    __syncthreads();
    if (lane == 0) red[wid] = sum;
    __syncthreads();
    sum = 0.f;
#pragma unroll
    for (int w = 0; w < 8; w++) sum += red[w];
    const float inv = 1.f / sum;

    for (int i = t; i < n4; i += 256) {
        float4 vv = p4[i];
        vv.x *= inv; vv.y *= inv; vv.z *= inv; vv.w *= inv;
        p4[i] = vv;
    }
}

// ---------------------------------------------------------------------------
extern "C" void kernel_launch(void* const* d_in, const int* in_sizes, int n_in,
                              void* d_out, int out_size)
{
    const float* q = (const float*)d_in[0];
    const float* k = (const float*)d_in[1];
    const float* v = (const float*)d_in[2];
    float* out = (float*)d_out;

    static float* S  = nullptr;
    static float* VT = nullptr;
    static bool init = false;
    if (!init) {
        cudaGetSymbolAddress((void**)&S, g_S);
        cudaGetSymbolAddress((void**)&VT, g_VT);
        cudaFuncSetAttribute(gemm_s_tf32,
                             cudaFuncAttributeMaxDynamicSharedMemorySize, T_SMEM);
        cudaFuncSetAttribute(gemm_pv_bf16,
                             cudaFuncAttributeMaxDynamicSharedMemorySize, B_SMEM);
        init = true;
    }

    // K0: VT = V^T
    {
        dim3 grid(DDIM / 32, NTOK / 32);
        transpose_kernel<<<grid, 256>>>(v, VT, NTOK, DDIM);
    }
    // K1: S = Q K^T   (K=1024 -> 32 iters)
    {
        dim3 grid(NTOK / 128, NTOK / 128);
        gemm_s_tf32<<<grid, 256, T_SMEM>>>(q, DDIM, k, DDIM, S, NTOK, DDIM / BK);
    }
    // K2: softmax rows of S
    softmax_kernel<<<NTOK, 256>>>(S, NTOK);
    // K3: out = P VT^T  (K=4096 -> 128 iters)
    {
        dim3 grid(DDIM / 128, NTOK / 128);
        gemm_pv_bf16<<<grid, 256, B_SMEM>>>(S, NTOK, VT, NTOK, out, DDIM, NTOK / BK);
    }
}

// round 17
// speedup vs baseline: 1.1321x; 1.1321x over previous
#include <cuda_runtime.h>
#include <cstdint>
#include <math_constants.h>

// out = softmax(Q K^T) V, N=4096, D=1024, fp32.
// tf32x3 mma.sync GEMMs with operands PRE-SPLIT into (hi,lo) tf32 planes by
// producer kernels, so the GEMM mainloop is pure cp.async + LDS + MMA
// (round-15 pipeline, minus its 27.5% ALU-pipe cvt storm).
//   K0a: Qhi/Qlo = split(Q)     K0b: Khi/Klo = split(K)
//   K0c: VThi/VTlo = split(V^T)
//   K1 : S = Q K^T        (gemm_planes, kIters=32)
//   K2 : Phi/Plo = softmax rows of S (split at write)
//   K3 : out = P VT^T     (gemm_planes, kIters=128)

#define NTOK 4096
#define DDIM 1024
#define BK 32

__device__ float g_S  [(size_t)NTOK * NTOK];    // raw scores
__device__ float g_Phi[(size_t)NTOK * NTOK];
__device__ float g_Plo[(size_t)NTOK * NTOK];
__device__ float g_Qhi[(size_t)NTOK * DDIM];
__device__ float g_Qlo[(size_t)NTOK * DDIM];
__device__ float g_Khi[(size_t)NTOK * DDIM];
__device__ float g_Klo[(size_t)NTOK * DDIM];
__device__ float g_VThi[(size_t)DDIM * NTOK];
__device__ float g_VTlo[(size_t)DDIM * NTOK];

// ---------------------------------------------------------------------------
__device__ __forceinline__ uint32_t smem_u32(const void* p) {
    uint32_t a;
    asm("{ .reg .u64 t; cvta.to.shared.u64 t, %1; cvt.u32.u64 %0, t; }"
        : "=r"(a) : "l"(p));
    return a;
}
__device__ __forceinline__ void cp_async16(uint32_t dst, const void* src) {
    asm volatile("cp.async.cg.shared.global [%0], [%1], 16;"
                 :: "r"(dst), "l"(src));
}
#define CP_COMMIT() asm volatile("cp.async.commit_group;" ::: "memory")
#define CP_WAIT2()  asm volatile("cp.async.wait_group 2;" ::: "memory")

__device__ __forceinline__ float tf_hi(float x) {
    uint32_t u;
    asm("cvt.rna.tf32.f32 %0, %1;" : "=r"(u) : "f"(x));
    return __uint_as_float(u);
}
__device__ __forceinline__ void mma_tf32(float* c, const uint32_t* a,
                                         const uint32_t* b) {
    asm volatile(
        "mma.sync.aligned.m16n8k8.row.col.f32.tf32.tf32.f32 "
        "{%0,%1,%2,%3}, {%4,%5,%6,%7}, {%8,%9}, {%0,%1,%2,%3};"
        : "+f"(c[0]), "+f"(c[1]), "+f"(c[2]), "+f"(c[3])
        : "r"(a[0]), "r"(a[1]), "r"(a[2]), "r"(a[3]), "r"(b[0]), "r"(b[1]));
}

// ===========================================================================
// gemm_planes: C[M,N] = (Ahi+Alo)[M,K] @ (Bhi+Blo)[N,K]^T, tf32x3.
// 128x128 CTA tile, BK=32, cp.async 3-stage, 256 threads (8 warps 2x4).
// Stage = 4 tiles (Ahi,Alo,Bhi,Blo), row stride 36 floats (conflict-free).
// ===========================================================================
#define AS_W 36
#define TILE_F (128 * AS_W)
#define STAGE_F (4 * TILE_F)
#define SMEM_BYTES (3 * STAGE_F * 4)   // 221184 B

__global__ __launch_bounds__(256, 1)
void gemm_planes(const float* __restrict__ Ahi_g, const float* __restrict__ Alo_g,
                 const float* __restrict__ Bhi_g, const float* __restrict__ Blo_g,
                 int lda, int ldb,
                 float* __restrict__ C, int ldc, int kIters)
{
    extern __shared__ float smf[];
    const uint32_t sb = smem_u32(smf);

    const int tid  = threadIdx.x;
    const int wid  = tid >> 5;
    const int lane = tid & 31;
    const int g    = lane >> 2;
    const int kq   = lane & 3;
    const int wm   = wid & 1;
    const int wn   = wid >> 1;
    const int m0   = blockIdx.y * 128;
    const int n0   = blockIdx.x * 128;

    int crow[4], ccol[4];
#pragma unroll
    for (int t = 0; t < 4; t++) {
        int idx = tid + 256 * t;
        crow[t] = idx >> 3;
        ccol[t] = idx & 7;
    }

    auto copy_stage = [&](int buf, int kChunk) {
        const int k0 = kChunk * BK;
        const uint32_t base = sb + (uint32_t)(buf * STAGE_F) * 4u;
#pragma unroll
        for (int t = 0; t < 4; t++) {
            const uint32_t off = (uint32_t)(crow[t] * AS_W + ccol[t] * 4) * 4u;
            const size_t sa = (size_t)(m0 + crow[t]) * lda + k0 + ccol[t] * 4;
            const size_t sbo = (size_t)(n0 + crow[t]) * ldb + k0 + ccol[t] * 4;
            cp_async16(base + off,                          Ahi_g + sa);
            cp_async16(base + off + (uint32_t)TILE_F * 4u,  Alo_g + sa);
            cp_async16(base + off + 2u * TILE_F * 4u,       Bhi_g + sbo);
            cp_async16(base + off + 3u * TILE_F * 4u,       Blo_g + sbo);
        }
    };

    float acc[4][4][4];
#pragma unroll
    for (int mt = 0; mt < 4; mt++)
#pragma unroll
        for (int nt = 0; nt < 4; nt++)
#pragma unroll
            for (int r = 0; r < 4; r++) acc[mt][nt][r] = 0.f;

    copy_stage(0, 0); CP_COMMIT();
    copy_stage(1, 1); CP_COMMIT();
    copy_stage(2, 2); CP_COMMIT();

    for (int i = 0; i < kIters; i++) {
        CP_WAIT2();
        __syncthreads();

        const int s = i % 3;
        const float* AsH = smf + s * STAGE_F;
        const float* AsL = AsH + TILE_F;
        const float* BsH = AsL + TILE_F;
        const float* BsL = BsH + TILE_F;

#pragma unroll
        for (int k8 = 0; k8 < BK / 8; k8++) {
            const int kc = k8 * 8 + kq;

            uint32_t Ah[4][4], Al[4][4], Bh[4][2], Bl[4][2];
#pragma unroll
            for (int mt = 0; mt < 4; mt++) {
                const int r0 = wm * 64 + mt * 16 + g;
                const int r1 = r0 + 8;
                Ah[mt][0] = __float_as_uint(AsH[r0 * AS_W + kc]);
                Ah[mt][1] = __float_as_uint(AsH[r1 * AS_W + kc]);
                Ah[mt][2] = __float_as_uint(AsH[r0 * AS_W + kc + 4]);
                Ah[mt][3] = __float_as_uint(AsH[r1 * AS_W + kc + 4]);
                Al[mt][0] = __float_as_uint(AsL[r0 * AS_W + kc]);
                Al[mt][1] = __float_as_uint(AsL[r1 * AS_W + kc]);
                Al[mt][2] = __float_as_uint(AsL[r0 * AS_W + kc + 4]);
                Al[mt][3] = __float_as_uint(AsL[r1 * AS_W + kc + 4]);
            }
#pragma unroll
            for (int nt = 0; nt < 4; nt++) {
                const int n = wn * 32 + nt * 8 + g;
                Bh[nt][0] = __float_as_uint(BsH[n * AS_W + kc]);
                Bh[nt][1] = __float_as_uint(BsH[n * AS_W + kc + 4]);
                Bl[nt][0] = __float_as_uint(BsL[n * AS_W + kc]);
                Bl[nt][1] = __float_as_uint(BsL[n * AS_W + kc + 4]);
            }
#pragma unroll
            for (int mt = 0; mt < 4; mt++)
#pragma unroll
                for (int nt = 0; nt < 4; nt++) {
                    mma_tf32(acc[mt][nt], Ah[mt], Bh[nt]);
                    mma_tf32(acc[mt][nt], Ah[mt], Bl[nt]);
                    mma_tf32(acc[mt][nt], Al[mt], Bh[nt]);
                }
        }

        __syncthreads();
        if (i + 3 < kIters) copy_stage(s, i + 3);
        CP_COMMIT();   // empty group keeps wait_group bookkeeping exact
    }

#pragma unroll
    for (int mt = 0; mt < 4; mt++) {
        const int r0 = m0 + wm * 64 + mt * 16 + g;
#pragma unroll
        for (int nt = 0; nt < 4; nt++) {
            const int col = n0 + wn * 32 + nt * 8 + kq * 2;
            *(float2*)(C + (size_t)r0 * ldc + col)       = make_float2(acc[mt][nt][0], acc[mt][nt][1]);
            *(float2*)(C + (size_t)(r0 + 8) * ldc + col) = make_float2(acc[mt][nt][2], acc[mt][nt][3]);
        }
    }
}

// ---------------------------------------------------------------------------
// split: hi = tf32(x), lo = tf32(x - hi)   (element-wise, float4)
// ---------------------------------------------------------------------------
__global__ __launch_bounds__(256)
void split_kernel(const float* __restrict__ in, float* __restrict__ hi,
                  float* __restrict__ lo, int n4)
{
    int i = blockIdx.x * 256 + threadIdx.x;
    if (i >= n4) return;
    float4 f = ((const float4*)in)[i];
    float4 h, l;
    h.x = tf_hi(f.x); l.x = tf_hi(f.x - h.x);
    h.y = tf_hi(f.y); l.y = tf_hi(f.y - h.y);
    h.z = tf_hi(f.z); l.z = tf_hi(f.z - h.z);
    h.w = tf_hi(f.w); l.w = tf_hi(f.w - h.w);
    ((float4*)hi)[i] = h;
    ((float4*)lo)[i] = l;
}

// ---------------------------------------------------------------------------
// transpose + split: VThi/VTlo[c][r] = split(V[r][c])
// ---------------------------------------------------------------------------
__global__ __launch_bounds__(256)
void transpose_split_kernel(const float* __restrict__ in,
                            float* __restrict__ ohi, float* __restrict__ olo,
                            int R, int Ccols)
{
    __shared__ float t[32][33];
    const int r0 = blockIdx.y * 32, c0 = blockIdx.x * 32;
    const int x = threadIdx.x & 31, y = threadIdx.x >> 5;
#pragma unroll
    for (int i = 0; i < 32; i += 8)
        t[y + i][x] = in[(size_t)(r0 + y + i) * Ccols + c0 + x];
    __syncthreads();
#pragma unroll
    for (int i = 0; i < 32; i += 8) {
        float v = t[x][y + i];
        float h = tf_hi(v);
        size_t o = (size_t)(c0 + y + i) * R + r0 + x;
        ohi[o] = h;
        olo[o] = tf_hi(v - h);
    }
}

// ---------------------------------------------------------------------------
// softmax rows of S -> Phi/Plo (split tf32 planes). One block per row.
// ---------------------------------------------------------------------------
__global__ __launch_bounds__(256)
void softmax_split_kernel(float* __restrict__ S, float* __restrict__ Phi,
                          float* __restrict__ Plo, int N)
{
    __shared__ float red[8];
    const int t    = threadIdx.x;
    const int lane = t & 31;
    const int wid  = t >> 5;
    float4* p4 = (float4*)(S + (size_t)blockIdx.x * N);
    float4* h4 = (float4*)(Phi + (size_t)blockIdx.x * N);
    float4* l4 = (float4*)(Plo + (size_t)blockIdx.x * N);
    const int n4 = N / 4;

    float m = -CUDART_INF_F;
    for (int i = t; i < n4; i += 256) {
        float4 vv = p4[i];
        m = fmaxf(m, fmaxf(fmaxf(vv.x, vv.y), fmaxf(vv.z, vv.w)));
    }
#pragma unroll
    for (int s = 16; s > 0; s >>= 1)
        m = fmaxf(m, __shfl_xor_sync(0xffffffffu, m, s));
    if (lane == 0) red[wid] = m;
    __syncthreads();
    m = red[0];
#pragma unroll
    for (int w = 1; w < 8; w++) m = fmaxf(m, red[w]);

    float sum = 0.f;
    for (int i = t; i < n4; i += 256) {
        float4 vv = p4[i];
        vv.x = __expf(vv.x - m);
        vv.y = __expf(vv.y - m);
        vv.z = __expf(vv.z - m);
        vv.w = __expf(vv.w - m);
        sum += (vv.x + vv.y) + (vv.z + vv.w);
        p4[i] = vv;
    }
#pragma unroll
    for (int s = 16; s > 0; s >>= 1)
        sum += __shfl_xor_sync(0xffffffffu, sum, s);
    __syncthreads();
    if (lane == 0) red[wid] = sum;
    __syncthreads();
    sum = 0.f;
#pragma unroll
    for (int w = 0; w < 8; w++) sum += red[w];
    const float inv = 1.f / sum;

    for (int i = t; i < n4; i += 256) {
        float4 vv = p4[i];
        float4 h, l;
        vv.x *= inv; h.x = tf_hi(vv.x); l.x = tf_hi(vv.x - h.x);
        vv.y *= inv; h.y = tf_hi(vv.y); l.y = tf_hi(vv.y - h.y);
        vv.z *= inv; h.z = tf_hi(vv.z); l.z = tf_hi(vv.z - h.z);
        vv.w *= inv; h.w = tf_hi(vv.w); l.w = tf_hi(vv.w - h.w);
        h4[i] = h;
        l4[i] = l;
    }
}

// ---------------------------------------------------------------------------
extern "C" void kernel_launch(void* const* d_in, const int* in_sizes, int n_in,
                              void* d_out, int out_size)
{
    const float* q = (const float*)d_in[0];
    const float* k = (const float*)d_in[1];
    const float* v = (const float*)d_in[2];
    float* out = (float*)d_out;

    static float *S, *Phi, *Plo, *Qhi, *Qlo, *Khi, *Klo, *VThi, *VTlo;
    static bool init = false;
    if (!init) {
        cudaGetSymbolAddress((void**)&S,    g_S);
        cudaGetSymbolAddress((void**)&Phi,  g_Phi);
        cudaGetSymbolAddress((void**)&Plo,  g_Plo);
        cudaGetSymbolAddress((void**)&Qhi,  g_Qhi);
        cudaGetSymbolAddress((void**)&Qlo,  g_Qlo);
        cudaGetSymbolAddress((void**)&Khi,  g_Khi);
        cudaGetSymbolAddress((void**)&Klo,  g_Klo);
        cudaGetSymbolAddress((void**)&VThi, g_VThi);
        cudaGetSymbolAddress((void**)&VTlo, g_VTlo);
        cudaFuncSetAttribute(gemm_planes,
                             cudaFuncAttributeMaxDynamicSharedMemorySize, SMEM_BYTES);
        init = true;
    }

    const int qkN4 = NTOK * DDIM / 4;

    // K0: splits
    split_kernel<<<(qkN4 + 255) / 256, 256>>>(q, Qhi, Qlo, qkN4);
    split_kernel<<<(qkN4 + 255) / 256, 256>>>(k, Khi, Klo, qkN4);
    {
        dim3 grid(DDIM / 32, NTOK / 32);
        transpose_split_kernel<<<grid, 256>>>(v, VThi, VTlo, NTOK, DDIM);
    }
    // K1: S = Q K^T
    {
        dim3 grid(NTOK / 128, NTOK / 128);
        gemm_planes<<<grid, 256, SMEM_BYTES>>>(Qhi, Qlo, Khi, Klo,
                                               DDIM, DDIM, S, NTOK, DDIM / BK);
    }
    // K2: softmax + split
    softmax_split_kernel<<<NTOK, 256>>>(S, Phi, Plo, NTOK);
    // K3: out = P VT^T
    {
        dim3 grid(DDIM / 128, NTOK / 128);
        gemm_planes<<<grid, 256, SMEM_BYTES>>>(Phi, Plo, VThi, VTlo,
                                               NTOK, NTOK, out, DDIM, NTOK / BK);
    }
}